// round 14
// baseline (speedup 1.0000x reference)
#include <cuda_runtime.h>
#include <cuda_bf16.h>
#include <cstdint>

// Problem constants
#define B_  8
#define T_  32
#define S_  512
#define F_  128
#define K_  64
#define N_  200

// Tiling
#define SI  32          // s-tile
#define FI  8           // f-tile
#define NT  128         // threads per block (4 warps)
#define PFD 4           // v register-prefetch depth (k-steps)

// SMEM: attnF [K][T] floats (8KB) during main loop; stgU (40KB) overlays after.
#define SMEM_TOTAL   ((T_/2)*SI*10*8)    // 40960
typedef unsigned long long ull;

// Packed f32x2 FMA: acc = v * a + acc   (lanes = two adjacent t's)
__device__ __forceinline__ void fma2(ull& acc, ull v, ull a) {
    asm("fma.rn.f32x2 %0, %1, %2, %0;" : "+l"(acc) : "l"(v), "l"(a));
}
// Duplicate one fp32 into both lanes of an f32x2 register pair.
__device__ __forceinline__ ull dup2(float w) {
    ull r;
    asm("mov.b64 %0, {%1, %1};" : "=l"(r) : "f"(w));
    return r;
}
// Streaming 8B global load (evict-first: V is read exactly once chip-wide)
__device__ __forceinline__ float2 ldcs2(const float* p) {
    float2 v;
    asm volatile("ld.global.cs.v2.f32 {%0, %1}, [%2];"
                 : "=f"(v.x), "=f"(v.y) : "l"(p));
    return v;
}

// ---------------------------------------------------------------------------
// Grid: (S/SI, F/FI, B) = (16,16,8) = 2048 blocks, 128 threads, 4 CTAs/SM.
// Thread (sg, fl): 2 s x 1 f x ALL 32 t (16 f32x2 t-pairs x 2 s = 64 regs).
// Each V element is read by exactly ONE thread -> no V smem at all.
// v stream: depth-4 register pipeline of LDG.64; attn broadcast from smem.
// ---------------------------------------------------------------------------
__global__ void __launch_bounds__(NT, 4)
fusion_kernel(const float* __restrict__ tgt,
              const float* __restrict__ V,
              const float* __restrict__ corr,
              const int*   __restrict__ tIdx,
              const int*   __restrict__ rIdx,
              float* __restrict__ out) {
    extern __shared__ char smem[];
    float* attnF = (float*)smem;       // [K][T] during main loop
    ull*   stgU  = (ull*)smem;         // overlays attnF after main loop

    const int b   = blockIdx.z;
    const int f0  = blockIdx.y * FI;
    const int s0  = blockIdx.x * SI;
    const int tid = threadIdx.x;
    const int wid  = tid >> 5;
    const int lane = tid & 31;

    const int sg = tid & 15;          // 0..15 : s-group (2 s each)
    const int fl = tid >> 4;          // 0..7  : f within tile

    // v stream pointer: this thread's 2 s-values for f = f0+fl, k varying
    const float* vp = V + (long)b * K_ * F_ * S_
                        + (long)(f0 + fl) * S_ + s0 + sg * 2;
    const long KSTRIDE = (long)F_ * S_;

    // --- start the v register pipeline BEFORE softmax (hides first latency) ---
    float2 vf[PFD];
    #pragma unroll
    for (int j = 0; j < PFD; ++j) vf[j] = ldcs2(vp + j * KSTRIDE);

    // --- softmax: 4 warps x 8 t's each, gather from L2-hot corr ---
    {
        int c0 = rIdx[lane];
        int c1 = rIdx[lane + 32];
        #pragma unroll
        for (int t = wid; t < T_; t += 4) {
            int row = tIdx[b * T_ + t];
            float v0 = __ldg(corr + row * N_ + c0);
            float v1 = __ldg(corr + row * N_ + c1);
            float m = fmaxf(v0, v1);
            #pragma unroll
            for (int off = 16; off > 0; off >>= 1)
                m = fmaxf(m, __shfl_xor_sync(0xffffffffu, m, off));
            float e0 = expf(v0 - m);
            float e1 = expf(v1 - m);
            float s = e0 + e1;
            #pragma unroll
            for (int off = 16; off > 0; off >>= 1)
                s += __shfl_xor_sync(0xffffffffu, s, off);
            float inv = 1.0f / s;
            attnF[lane * T_ + t]        = e0 * inv;
            attnF[(lane + 32) * T_ + t] = e1 * inv;
        }
    }
    __syncthreads();   // attnF visible; only barrier before staging

    // --- main loop: v from registers (global stream), attn broadcast LDS ---
    ull acc[16][2];
    #pragma unroll
    for (int p = 0; p < 16; ++p) { acc[p][0] = 0ULL; acc[p][1] = 0ULL; }

    #pragma unroll 4
    for (int k = 0; k < K_; ++k) {
        float2 cur = vf[k & (PFD - 1)];
        if (k + PFD < K_)
            vf[k & (PFD - 1)] = ldcs2(vp + (long)(k + PFD) * KSTRIDE);
        ull vd0 = dup2(cur.x), vd1 = dup2(cur.y);

        const float* aF = attnF + k * T_;
        ulonglong2 a01 = *(const ulonglong2*)(aF);
        ulonglong2 a23 = *(const ulonglong2*)(aF + 4);
        ulonglong2 a45 = *(const ulonglong2*)(aF + 8);
        ulonglong2 a67 = *(const ulonglong2*)(aF + 12);
        ulonglong2 a89 = *(const ulonglong2*)(aF + 16);
        ulonglong2 aAB = *(const ulonglong2*)(aF + 20);
        ulonglong2 aCD = *(const ulonglong2*)(aF + 24);
        ulonglong2 aEF = *(const ulonglong2*)(aF + 28);

        fma2(acc[0][0],  vd0, a01.x); fma2(acc[0][1],  vd1, a01.x);
        fma2(acc[1][0],  vd0, a01.y); fma2(acc[1][1],  vd1, a01.y);
        fma2(acc[2][0],  vd0, a23.x); fma2(acc[2][1],  vd1, a23.x);
        fma2(acc[3][0],  vd0, a23.y); fma2(acc[3][1],  vd1, a23.y);
        fma2(acc[4][0],  vd0, a45.x); fma2(acc[4][1],  vd1, a45.x);
        fma2(acc[5][0],  vd0, a45.y); fma2(acc[5][1],  vd1, a45.y);
        fma2(acc[6][0],  vd0, a67.x); fma2(acc[6][1],  vd1, a67.x);
        fma2(acc[7][0],  vd0, a67.y); fma2(acc[7][1],  vd1, a67.y);
        fma2(acc[8][0],  vd0, a89.x); fma2(acc[8][1],  vd1, a89.x);
        fma2(acc[9][0],  vd0, a89.y); fma2(acc[9][1],  vd1, a89.y);
        fma2(acc[10][0], vd0, aAB.x); fma2(acc[10][1], vd1, aAB.x);
        fma2(acc[11][0], vd0, aAB.y); fma2(acc[11][1], vd1, aAB.y);
        fma2(acc[12][0], vd0, aCD.x); fma2(acc[12][1], vd1, aCD.x);
        fma2(acc[13][0], vd0, aCD.y); fma2(acc[13][1], vd1, aCD.y);
        fma2(acc[14][0], vd0, aEF.x); fma2(acc[14][1], vd1, aEF.x);
        fma2(acc[15][0], vd0, aEF.y); fma2(acc[15][1], vd1, aEF.y);
    }
    __syncthreads();   // all attnF reads done; stgU may overlay

    // --- stage: stgU[tpair][s][10] (fl at 0..7, 2 pad) ---
    #pragma unroll
    for (int p = 0; p < 16; ++p) {
        #pragma unroll
        for (int si = 0; si < 2; ++si) {
            int s = sg * 2 + si;
            stgU[(p * SI + s) * 10 + fl] = acc[p][si];
        }
    }
    __syncthreads();

    // --- epilogue: per iter read 4 ull (2 x LDS.128) -> two float4 RMW ---
    #pragma unroll
    for (int i = tid; i < (T_ / 2) * SI * 2; i += NT) {
        int g  = i & 1;
        int s  = (i >> 1) & (SI - 1);
        int tp = i >> 6;
        const ull* src = &stgU[(tp * SI + s) * 10 + 4 * g];
        ulonglong2 u0 = *(const ulonglong2*)(src);       // f = 4g, 4g+1
        ulonglong2 u1 = *(const ulonglong2*)(src + 2);   // f = 4g+2, 4g+3
        float2 p0 = *(const float2*)&u0.x;  // (t_even, t_odd)
        float2 p1 = *(const float2*)&u0.y;
        float2 p2 = *(const float2*)&u1.x;
        float2 p3 = *(const float2*)&u1.y;

        long gi0 = (((long)b * T_ + 2 * tp)     * S_ + s0 + s) * F_ + f0 + 4 * g;
        long gi1 = (((long)b * T_ + 2 * tp + 1) * S_ + s0 + s) * F_ + f0 + 4 * g;
        float4 t4, c4;
        t4 = *(const float4*)(tgt + gi0);
        c4.x = p0.x + t4.x; c4.y = p1.x + t4.y;
        c4.z = p2.x + t4.z; c4.w = p3.x + t4.w;
        *(float4*)(out + gi0) = c4;
        t4 = *(const float4*)(tgt + gi1);
        c4.x = p0.y + t4.x; c4.y = p1.y + t4.y;
        c4.z = p2.y + t4.z; c4.w = p3.y + t4.w;
        *(float4*)(out + gi1) = c4;
    }
}

// ---------------------------------------------------------------------------
extern "C" void kernel_launch(void* const* d_in, const int* in_sizes, int n_in,
                              void* d_out, int out_size) {
    const float* tgt  = nullptr;   // 16777216
    const float* V    = nullptr;   // 33554432
    const float* corr = nullptr;   // 40000
    const int*   tIdx = nullptr;   // 256   (int32: jax x64 disabled)
    const int*   rIdx = nullptr;   // 64

    for (int i = 0; i < n_in; ++i) {
        switch (in_sizes[i]) {
            case 16777216: tgt  = (const float*)d_in[i]; break;
            case 33554432: V    = (const float*)d_in[i]; break;
            case 40000:    corr = (const float*)d_in[i]; break;
            case 256:      tIdx = (const int*)d_in[i]; break;
            case 64:       rIdx = (const int*)d_in[i]; break;
            default: break;
        }
    }

    cudaFuncSetAttribute(fusion_kernel,
                         cudaFuncAttributeMaxDynamicSharedMemorySize,
                         SMEM_TOTAL);

    dim3 grid(S_ / SI, F_ / FI, B_);
    fusion_kernel<<<grid, NT, SMEM_TOTAL>>>(tgt, V, corr, tIdx, rIdx,
                                            (float*)d_out);
}

// round 15
// speedup vs baseline: 1.0038x; 1.0038x over previous
#include <cuda_runtime.h>
#include <cuda_bf16.h>

// Problem constants
#define B_  8
#define T_  32
#define S_  512
#define F_  128
#define K_  64
#define N_  200

// Tiling
#define SI  32          // s-tile
#define FI  8           // f-tile
#define NT  128         // threads per block (4 warps)
#define KC  16          // k's per pipeline chunk
#define NCHUNK (K_/KC)  // 4

// SMEM (bytes):
//   Vbuf:  2 x KC*FI*SI floats = 32768 (double buffer)
//   attnF: K*T floats          = 8192
//   stgU:  (T/2)*SI*10 ull     = 40960 (overlays Vbuf+attnF after main loop)
#define SMEM_VBUF_BYTES  (KC*FI*SI*4)
#define SMEM_ATTN_BYTES  (K_*T_*4)
#define SMEM_TOTAL       (2*SMEM_VBUF_BYTES + SMEM_ATTN_BYTES)   // 40960

typedef unsigned long long ull;

// Packed f32x2 FMA: acc = v * a + acc   (lanes = two adjacent t's)
__device__ __forceinline__ void fma2(ull& acc, ull v, ull a) {
    asm("fma.rn.f32x2 %0, %1, %2, %0;" : "+l"(acc) : "l"(v), "l"(a));
}
// Duplicate one fp32 into both lanes of an f32x2 register pair.
__device__ __forceinline__ ull dup2(float w) {
    ull r;
    asm("mov.b64 %0, {%1, %1};" : "=l"(r) : "f"(w));
    return r;
}
// 16B async copy global -> shared
__device__ __forceinline__ void cp_async16(float* smem_dst, const float* gsrc) {
    unsigned s = (unsigned)__cvta_generic_to_shared(smem_dst);
    asm volatile("cp.async.cg.shared.global [%0], [%1], 16;" :: "r"(s), "l"(gsrc));
}
__device__ __forceinline__ void cp_commit() {
    asm volatile("cp.async.commit_group;");
}
template <int N>
__device__ __forceinline__ void cp_wait() {
    asm volatile("cp.async.wait_group %0;" :: "n"(N));
}
// Named pair barrier: 64 threads (two warps), id 1 or 2.
__device__ __forceinline__ void bar_pair(int id) {
    asm volatile("bar.sync %0, 64;" :: "r"(id) : "memory");
}

// ---------------------------------------------------------------------------
// Grid: (S/SI, F/FI, B) = (16,16,8) = 2048 blocks, 128 threads, 5 CTAs/SM.
// Thread (sg, fl, tq): 4 s x 1 f x 16 t (8 f32x2 t-pairs).  [R6 structure]
// Warp pairs {0,2} (fl 0-3) and {1,3} (fl 4-7) own disjoint V rows:
// fill + chunk sync are PAIR-scoped named barriers (no block convoy).
// ---------------------------------------------------------------------------
__global__ void __launch_bounds__(NT, 5)
fusion_kernel(const float* __restrict__ tgt,
              const float* __restrict__ V,
              const float* __restrict__ corr,
              const int*   __restrict__ tIdx,
              const int*   __restrict__ rIdx,
              float* __restrict__ out) {
    extern __shared__ char smem[];
    float* Vb[2] = { (float*)smem, (float*)(smem + SMEM_VBUF_BYTES) };
    float* attnF = (float*)(smem + 2 * SMEM_VBUF_BYTES);   // [K][T]
    ull*   stgU  = (ull*)smem;                              // overlay after loop

    const int b   = blockIdx.z;
    const int f0  = blockIdx.y * FI;
    const int s0  = blockIdx.x * SI;
    const int tid = threadIdx.x;
    const int wid  = tid >> 5;
    const int lane = tid & 31;

    const int pid   = wid & 1;                 // pair id: {0,2}->0, {1,3}->1
    const int plane = lane + 32 * (wid >> 1);  // 0..63 within pair

    const float* Vg = V + (long)b * K_ * F_ * S_ + (long)f0 * S_ + s0;

    // Pair-scoped fill: pair pid fills f rows {4*pid .. 4*pid+3} of chunk c.
    // 512 16B-units per pair per chunk -> 8 cp.async per thread.
    auto fill = [&](int c) {
        float* dst = Vb[c & 1];
        const float* src = Vg + (long)c * KC * F_ * S_;
        #pragma unroll
        for (int i = plane; i < KC * 4 * 8; i += 64) {
            int k  = i >> 5;
            int f  = pid * 4 + ((i >> 3) & 3);
            int s4 = i & 7;
            cp_async16(dst + (k * FI + f) * SI + s4 * 4,
                       src + ((long)k * F_ + f) * S_ + s4 * 4);
        }
        cp_commit();
    };

    // --- prefetch chunk 0 (latency hidden under softmax) ---
    fill(0);

    // --- softmax: 4 warps x 8 t's each, gather from L2-hot corr ---
    {
        int c0 = rIdx[lane];
        int c1 = rIdx[lane + 32];
        #pragma unroll
        for (int t = wid; t < T_; t += 4) {
            int row = tIdx[b * T_ + t];
            float v0 = __ldg(corr + row * N_ + c0);
            float v1 = __ldg(corr + row * N_ + c1);
            float m = fmaxf(v0, v1);
            #pragma unroll
            for (int off = 16; off > 0; off >>= 1)
                m = fmaxf(m, __shfl_xor_sync(0xffffffffu, m, off));
            float e0 = expf(v0 - m);
            float e1 = expf(v1 - m);
            float s = e0 + e1;
            #pragma unroll
            for (int off = 16; off > 0; off >>= 1)
                s += __shfl_xor_sync(0xffffffffu, s, off);
            float inv = 1.0f / s;
            attnF[lane * T_ + t]        = e0 * inv;
            attnF[(lane + 32) * T_ + t] = e1 * inv;
        }
    }
    __syncthreads();   // attnF visible to all warps (only full barrier pre-loop)

    // --- main loop: double-buffered k-chunks, PAIR-scoped sync ---
    const int sg = tid & 7;           // 0..7 : s-group (4 s each)
    const int fl = (tid >> 3) & 7;    // 0..7 : f within tile
    const int tq = tid >> 6;          // 0..1 : t-half
    const int t0 = tq * 16;

    ull acc[8][4];
    #pragma unroll
    for (int p = 0; p < 8; ++p)
        #pragma unroll
        for (int si = 0; si < 4; ++si) acc[p][si] = 0ULL;

    #pragma unroll
    for (int c = 0; c < NCHUNK; ++c) {
        if (c + 1 < NCHUNK) {
            fill(c + 1);
            cp_wait<1>();   // this thread's chunk-c copies done
        } else {
            cp_wait<0>();
        }
        bar_pair(1 + pid);  // pair-wide: chunk c rows (this pair's f) visible

        const float* Vc = Vb[c & 1];
        const float* aFc = attnF + c * KC * T_;
        #pragma unroll 4
        for (int k = 0; k < KC; ++k) {
            float4 vf = *(const float4*)(Vc + (k * FI + fl) * SI + sg * 4);
            ull vd0 = dup2(vf.x), vd1 = dup2(vf.y);
            ull vd2 = dup2(vf.z), vd3 = dup2(vf.w);
            const float* aF = aFc + k * T_ + t0;
            // t-half A (8 t): fewer live attn regs
            {
                ulonglong2 a01 = *(const ulonglong2*)(aF);
                ulonglong2 a23 = *(const ulonglong2*)(aF + 4);
                fma2(acc[0][0], vd0, a01.x); fma2(acc[0][1], vd1, a01.x);
                fma2(acc[0][2], vd2, a01.x); fma2(acc[0][3], vd3, a01.x);
                fma2(acc[1][0], vd0, a01.y); fma2(acc[1][1], vd1, a01.y);
                fma2(acc[1][2], vd2, a01.y); fma2(acc[1][3], vd3, a01.y);
                fma2(acc[2][0], vd0, a23.x); fma2(acc[2][1], vd1, a23.x);
                fma2(acc[2][2], vd2, a23.x); fma2(acc[2][3], vd3, a23.x);
                fma2(acc[3][0], vd0, a23.y); fma2(acc[3][1], vd1, a23.y);
                fma2(acc[3][2], vd2, a23.y); fma2(acc[3][3], vd3, a23.y);
            }
            // t-half B (8 t)
            {
                ulonglong2 a45 = *(const ulonglong2*)(aF + 8);
                ulonglong2 a67 = *(const ulonglong2*)(aF + 12);
                fma2(acc[4][0], vd0, a45.x); fma2(acc[4][1], vd1, a45.x);
                fma2(acc[4][2], vd2, a45.x); fma2(acc[4][3], vd3, a45.x);
                fma2(acc[5][0], vd0, a45.y); fma2(acc[5][1], vd1, a45.y);
                fma2(acc[5][2], vd2, a45.y); fma2(acc[5][3], vd3, a45.y);
                fma2(acc[6][0], vd0, a67.x); fma2(acc[6][1], vd1, a67.x);
                fma2(acc[6][2], vd2, a67.x); fma2(acc[6][3], vd3, a67.x);
                fma2(acc[7][0], vd0, a67.y); fma2(acc[7][1], vd1, a67.y);
                fma2(acc[7][2], vd2, a67.y); fma2(acc[7][3], vd3, a67.y);
            }
        }
        bar_pair(1 + pid);  // pair done reading buf (c&1) before its refill
    }
    __syncthreads();   // ALL warps done (stg overlays both pairs' V rows)

    // --- stage: stgU[tpair][s][10] (fl at 0..7, 2 pad) ---
    #pragma unroll
    for (int p = 0; p < 8; ++p) {
        int tp = tq * 8 + p;
        #pragma unroll
        for (int si = 0; si < 4; ++si) {
            int s = sg * 4 + si;
            stgU[(tp * SI + s) * 10 + fl] = acc[p][si];
        }
    }
    __syncthreads();

    // --- epilogue: per iter read 4 ull (2 x LDS.128) -> two float4 RMW ---
    #pragma unroll
    for (int i = tid; i < (T_ / 2) * SI * 2; i += NT) {
        int g  = i & 1;
        int s  = (i >> 1) & (SI - 1);
        int tp = i >> 6;
        const ull* src = &stgU[(tp * SI + s) * 10 + 4 * g];
        ulonglong2 u0 = *(const ulonglong2*)(src);       // f = 4g, 4g+1
        ulonglong2 u1 = *(const ulonglong2*)(src + 2);   // f = 4g+2, 4g+3
        float2 p0 = *(const float2*)&u0.x;  // (t_even, t_odd)
        float2 p1 = *(const float2*)&u0.y;
        float2 p2 = *(const float2*)&u1.x;
        float2 p3 = *(const float2*)&u1.y;

        long gi0 = (((long)b * T_ + 2 * tp)     * S_ + s0 + s) * F_ + f0 + 4 * g;
        long gi1 = (((long)b * T_ + 2 * tp + 1) * S_ + s0 + s) * F_ + f0 + 4 * g;
        float4 t4, c4;
        t4 = *(const float4*)(tgt + gi0);
        c4.x = p0.x + t4.x; c4.y = p1.x + t4.y;
        c4.z = p2.x + t4.z; c4.w = p3.x + t4.w;
        *(float4*)(out + gi0) = c4;
        t4 = *(const float4*)(tgt + gi1);
        c4.x = p0.y + t4.x; c4.y = p1.y + t4.y;
        c4.z = p2.y + t4.z; c4.w = p3.y + t4.w;
        *(float4*)(out + gi1) = c4;
    }
}

// ---------------------------------------------------------------------------
extern "C" void kernel_launch(void* const* d_in, const int* in_sizes, int n_in,
                              void* d_out, int out_size) {
    const float* tgt  = nullptr;   // 16777216
    const float* V    = nullptr;   // 33554432
    const float* corr = nullptr;   // 40000
    const int*   tIdx = nullptr;   // 256   (int32: jax x64 disabled)
    const int*   rIdx = nullptr;   // 64

    for (int i = 0; i < n_in; ++i) {
        switch (in_sizes[i]) {
            case 16777216: tgt  = (const float*)d_in[i]; break;
            case 33554432: V    = (const float*)d_in[i]; break;
            case 40000:    corr = (const float*)d_in[i]; break;
            case 256:      tIdx = (const int*)d_in[i]; break;
            case 64:       rIdx = (const int*)d_in[i]; break;
            default: break;
        }
    }

    cudaFuncSetAttribute(fusion_kernel,
                         cudaFuncAttributeMaxDynamicSharedMemorySize,
                         SMEM_TOTAL);

    dim3 grid(S_ / SI, F_ / FI, B_);
    fusion_kernel<<<grid, NT, SMEM_TOTAL>>>(tgt, V, corr, tIdx, rIdx,
                                            (float*)d_out);
}

// round 16
// speedup vs baseline: 1.1123x; 1.1081x over previous
#include <cuda_runtime.h>
#include <cuda_bf16.h>

// Problem constants
#define B_  8
#define T_  32
#define S_  512
#define F_  128
#define K_  64
#define N_  200

// Tiling
#define SI  32          // s-tile
#define FI  8           // f-tile
#define NT  128         // threads per block (4 warps)
#define KC  16          // k's per pipeline chunk
#define NCHUNK (K_/KC)  // 4

// SMEM (bytes):
//   Vbuf:  2 x KC*FI*SI floats = 32768 (double buffer)
//   attnF: K*T floats          = 8192
//   stgF:  T*SI*10 floats      = 40960 (overlays Vbuf+attnF after main loop)
#define SMEM_VBUF_BYTES  (KC*FI*SI*4)
#define SMEM_ATTN_BYTES  (K_*T_*4)
#define SMEM_TOTAL       (2*SMEM_VBUF_BYTES + SMEM_ATTN_BYTES)   // 40960

typedef unsigned long long ull;

// Packed f32x2 FMA: acc = v * a + acc   (lanes = two adjacent t's)
__device__ __forceinline__ void fma2(ull& acc, ull v, ull a) {
    asm("fma.rn.f32x2 %0, %1, %2, %0;" : "+l"(acc) : "l"(v), "l"(a));
}
// Duplicate one fp32 into both lanes of an f32x2 register pair.
__device__ __forceinline__ ull dup2(float w) {
    ull r;
    asm("mov.b64 %0, {%1, %1};" : "=l"(r) : "f"(w));
    return r;
}
// 16B async copy global -> shared
__device__ __forceinline__ void cp_async16(float* smem_dst, const float* gsrc) {
    unsigned s = (unsigned)__cvta_generic_to_shared(smem_dst);
    asm volatile("cp.async.cg.shared.global [%0], [%1], 16;" :: "r"(s), "l"(gsrc));
}
__device__ __forceinline__ void cp_commit() {
    asm volatile("cp.async.commit_group;");
}
template <int N>
__device__ __forceinline__ void cp_wait() {
    asm volatile("cp.async.wait_group %0;" :: "n"(N));
}

// ---------------------------------------------------------------------------
// Grid: (S/SI, F/FI, B) = (16,16,8) = 2048 blocks, 128 threads, 4 CTAs/SM.
// Thread (sg, fl, tq): 4 s x 1 f x 16 t (8 f32x2 t-pairs).  [R6 structure]
// Stage/epilogue rebuilt for bank-conflict-free / dense smem transpose.
// ---------------------------------------------------------------------------
__global__ void __launch_bounds__(NT, 4)
fusion_kernel(const float* __restrict__ tgt,
              const float* __restrict__ V,
              const float* __restrict__ corr,
              const int*   __restrict__ tIdx,
              const int*   __restrict__ rIdx,
              float* __restrict__ out) {
    extern __shared__ char smem[];
    float* Vb[2] = { (float*)smem, (float*)(smem + SMEM_VBUF_BYTES) };
    float* attnF = (float*)(smem + 2 * SMEM_VBUF_BYTES);   // [K][T]
    float* stgF  = (float*)smem;                            // [T][SI][10] overlay

    const int b   = blockIdx.z;
    const int f0  = blockIdx.y * FI;
    const int s0  = blockIdx.x * SI;
    const int tid = threadIdx.x;
    const int wid  = tid >> 5;
    const int lane = tid & 31;

    const float* Vg = V + (long)b * K_ * F_ * S_ + (long)f0 * S_ + s0;

    // --- prefetch chunk 0 (latency hidden under softmax) ---
    {
        #pragma unroll
        for (int i = tid; i < KC * FI * (SI / 4); i += NT) {
            int k  = i / (FI * (SI / 4));
            int f  = (i / (SI / 4)) % FI;
            int s4 = i % (SI / 4);
            cp_async16(Vb[0] + (k * FI + f) * SI + s4 * 4,
                       Vg + ((long)k * F_ + f) * S_ + s4 * 4);
        }
        cp_commit();
    }

    // --- softmax: 4 warps x 8 t's each, gather from L2-hot corr ---
    {
        int c0 = rIdx[lane];
        int c1 = rIdx[lane + 32];
        #pragma unroll
        for (int t = wid; t < T_; t += 4) {
            int row = tIdx[b * T_ + t];
            float v0 = __ldg(corr + row * N_ + c0);
            float v1 = __ldg(corr + row * N_ + c1);
            float m = fmaxf(v0, v1);
            #pragma unroll
            for (int off = 16; off > 0; off >>= 1)
                m = fmaxf(m, __shfl_xor_sync(0xffffffffu, m, off));
            float e0 = expf(v0 - m);
            float e1 = expf(v1 - m);
            float s = e0 + e1;
            #pragma unroll
            for (int off = 16; off > 0; off >>= 1)
                s += __shfl_xor_sync(0xffffffffu, s, off);
            float inv = 1.0f / s;
            attnF[lane * T_ + t]        = e0 * inv;
            attnF[(lane + 32) * T_ + t] = e1 * inv;
        }
    }

    // --- main loop: double-buffered k-chunks ---
    const int sg = tid & 7;           // 0..7 : s-group (4 s each)
    const int fl = (tid >> 3) & 7;    // 0..7 : f within tile
    const int tq = tid >> 6;          // 0..1 : t-half
    const int t0 = tq * 16;

    ull acc[8][4];
    #pragma unroll
    for (int p = 0; p < 8; ++p)
        #pragma unroll
        for (int si = 0; si < 4; ++si) acc[p][si] = 0ULL;

    #pragma unroll
    for (int c = 0; c < NCHUNK; ++c) {
        if (c + 1 < NCHUNK) {
            float* dst = Vb[(c + 1) & 1];
            const float* src = Vg + (long)(c + 1) * KC * F_ * S_;
            #pragma unroll
            for (int i = tid; i < KC * FI * (SI / 4); i += NT) {
                int k  = i / (FI * (SI / 4));
                int f  = (i / (SI / 4)) % FI;
                int s4 = i % (SI / 4);
                cp_async16(dst + (k * FI + f) * SI + s4 * 4,
                           src + ((long)k * F_ + f) * S_ + s4 * 4);
            }
            cp_commit();
            cp_wait<1>();   // chunk c resident
        } else {
            cp_wait<0>();
        }
        __syncthreads();    // publishes chunk (and attnF on c==0)

        const float* Vc = Vb[c & 1];
        const float* aFc = attnF + c * KC * T_;
        #pragma unroll 4
        for (int k = 0; k < KC; ++k) {
            float4 vf = *(const float4*)(Vc + (k * FI + fl) * SI + sg * 4);
            ull vd0 = dup2(vf.x), vd1 = dup2(vf.y);
            ull vd2 = dup2(vf.z), vd3 = dup2(vf.w);
            const float* aF = aFc + k * T_ + t0;
            ulonglong2 a01 = *(const ulonglong2*)(aF);
            ulonglong2 a23 = *(const ulonglong2*)(aF + 4);
            ulonglong2 a45 = *(const ulonglong2*)(aF + 8);
            ulonglong2 a67 = *(const ulonglong2*)(aF + 12);
            fma2(acc[0][0], vd0, a01.x); fma2(acc[0][1], vd1, a01.x);
            fma2(acc[0][2], vd2, a01.x); fma2(acc[0][3], vd3, a01.x);
            fma2(acc[1][0], vd0, a01.y); fma2(acc[1][1], vd1, a01.y);
            fma2(acc[1][2], vd2, a01.y); fma2(acc[1][3], vd3, a01.y);
            fma2(acc[2][0], vd0, a23.x); fma2(acc[2][1], vd1, a23.x);
            fma2(acc[2][2], vd2, a23.x); fma2(acc[2][3], vd3, a23.x);
            fma2(acc[3][0], vd0, a23.y); fma2(acc[3][1], vd1, a23.y);
            fma2(acc[3][2], vd2, a23.y); fma2(acc[3][3], vd3, a23.y);
            fma2(acc[4][0], vd0, a45.x); fma2(acc[4][1], vd1, a45.x);
            fma2(acc[4][2], vd2, a45.x); fma2(acc[4][3], vd3, a45.x);
            fma2(acc[5][0], vd0, a45.y); fma2(acc[5][1], vd1, a45.y);
            fma2(acc[5][2], vd2, a45.y); fma2(acc[5][3], vd3, a45.y);
            fma2(acc[6][0], vd0, a67.x); fma2(acc[6][1], vd1, a67.x);
            fma2(acc[6][2], vd2, a67.x); fma2(acc[6][3], vd3, a67.x);
            fma2(acc[7][0], vd0, a67.y); fma2(acc[7][1], vd1, a67.y);
            fma2(acc[7][2], vd2, a67.y); fma2(acc[7][3], vd3, a67.y);
        }
        __syncthreads();    // all reads of buf (c&1) done before refill
    }

    // --- stage: unpack to stgF[t][s][10] floats, STS.32 (<=2-way banks) ---
    #pragma unroll
    for (int p = 0; p < 8; ++p) {
        int t = t0 + 2 * p;
        #pragma unroll
        for (int si = 0; si < 4; ++si) {
            int s = sg * 4 + si;
            ull a = acc[p][si];
            stgF[(t * SI + s) * 10 + fl]       = __uint_as_float((unsigned)(a & 0xffffffffULL));
            stgF[((t + 1) * SI + s) * 10 + fl] = __uint_as_float((unsigned)(a >> 32));
        }
    }
    __syncthreads();

    // --- epilogue: 2 x LDS.64 (8B-aligned, dense) -> float4 global RMW ---
    #pragma unroll
    for (int i = tid; i < T_ * SI * 2; i += NT) {   // 16 iters/thread
        int g = i & 1;
        int s = (i >> 1) & (SI - 1);
        int t = i >> 6;
        const float* src = stgF + (t * SI + s) * 10 + 4 * g;
        float2 lo = *(const float2*)(src);
        float2 hi = *(const float2*)(src + 2);
        long gi = (((long)b * T_ + t) * S_ + s0 + s) * F_ + f0 + 4 * g;
        float4 t4 = *(const float4*)(tgt + gi);
        float4 c4;
        c4.x = lo.x + t4.x; c4.y = lo.y + t4.y;
        c4.z = hi.x + t4.z; c4.w = hi.y + t4.w;
        *(float4*)(out + gi) = c4;
    }
}

// ---------------------------------------------------------------------------
extern "C" void kernel_launch(void* const* d_in, const int* in_sizes, int n_in,
                              void* d_out, int out_size) {
    const float* tgt  = nullptr;   // 16777216
    const float* V    = nullptr;   // 33554432
    const float* corr = nullptr;   // 40000
    const int*   tIdx = nullptr;   // 256   (int32: jax x64 disabled)
    const int*   rIdx = nullptr;   // 64

    for (int i = 0; i < n_in; ++i) {
        switch (in_sizes[i]) {
            case 16777216: tgt  = (const float*)d_in[i]; break;
            case 33554432: V    = (const float*)d_in[i]; break;
            case 40000:    corr = (const float*)d_in[i]; break;
            case 256:      tIdx = (const int*)d_in[i]; break;
            case 64:       rIdx = (const int*)d_in[i]; break;
            default: break;
        }
    }

    cudaFuncSetAttribute(fusion_kernel,
                         cudaFuncAttributeMaxDynamicSharedMemorySize,
                         SMEM_TOTAL);

    dim3 grid(S_ / SI, F_ / FI, B_);
    fusion_kernel<<<grid, NT, SMEM_TOTAL>>>(tgt, V, corr, tIdx, rIdx,
                                            (float*)d_out);
}

// round 17
// speedup vs baseline: 1.1163x; 1.0035x over previous
#include <cuda_runtime.h>
#include <cuda_bf16.h>

// Problem constants
#define B_  8
#define T_  32
#define S_  512
#define F_  128
#define K_  64
#define N_  200

// Tiling
#define SI  32          // s-tile
#define FI  8           // f-tile
#define NT  128         // threads per block (4 warps)
#define KC  16          // k's per pipeline chunk
#define NCHUNK (K_/KC)  // 4

// SMEM (bytes):
//   Vbuf:  2 x KC*FI*SI floats = 32768 (double buffer)
//   attnF: K*T floats          = 8192
//   stgU:  (T/2)*SI*10 ull     = 40960 (overlays Vbuf+attnF after main loop)
#define SMEM_VBUF_BYTES  (KC*FI*SI*4)
#define SMEM_ATTN_BYTES  (K_*T_*4)
#define SMEM_TOTAL       (2*SMEM_VBUF_BYTES + SMEM_ATTN_BYTES)   // 40960

typedef unsigned long long ull;

// Packed f32x2 FMA: acc = v * a + acc   (lanes = two adjacent t's)
__device__ __forceinline__ void fma2(ull& acc, ull v, ull a) {
    asm("fma.rn.f32x2 %0, %1, %2, %0;" : "+l"(acc) : "l"(v), "l"(a));
}
// Duplicate one fp32 into both lanes of an f32x2 register pair.
__device__ __forceinline__ ull dup2(float w) {
    ull r;
    asm("mov.b64 %0, {%1, %1};" : "=l"(r) : "f"(w));
    return r;
}
// 16B async copy global -> shared
__device__ __forceinline__ void cp_async16(float* smem_dst, const float* gsrc) {
    unsigned s = (unsigned)__cvta_generic_to_shared(smem_dst);
    asm volatile("cp.async.cg.shared.global [%0], [%1], 16;" :: "r"(s), "l"(gsrc));
}
__device__ __forceinline__ void cp_commit() {
    asm volatile("cp.async.commit_group;");
}
template <int N>
__device__ __forceinline__ void cp_wait() {
    asm volatile("cp.async.wait_group %0;" :: "n"(N));
}

// ---------------------------------------------------------------------------
// Grid: (S/SI, F/FI, B) = (16,16,8) = 2048 blocks, 128 threads, 4 CTAs/SM.
// Thread (sg, fl, tq): 4 s x 1 f x 16 t (8 f32x2 t-pairs).  [R6 structure]
// Chunk loop uses ONE barrier per chunk: the publish barrier for chunk c
// also certifies all warps finished chunk c-1, which is the only condition
// fill(c+1) needs before overwriting c-1's buffer.
// ---------------------------------------------------------------------------
__global__ void __launch_bounds__(NT, 4)
fusion_kernel(const float* __restrict__ tgt,
              const float* __restrict__ V,
              const float* __restrict__ corr,
              const int*   __restrict__ tIdx,
              const int*   __restrict__ rIdx,
              float* __restrict__ out) {
    extern __shared__ char smem[];
    float* Vb[2] = { (float*)smem, (float*)(smem + SMEM_VBUF_BYTES) };
    float* attnF = (float*)(smem + 2 * SMEM_VBUF_BYTES);   // [K][T]
    ull*   stgU  = (ull*)smem;                              // overlay after loop

    const int b   = blockIdx.z;
    const int f0  = blockIdx.y * FI;
    const int s0  = blockIdx.x * SI;
    const int tid = threadIdx.x;
    const int wid  = tid >> 5;
    const int lane = tid & 31;

    const float* Vg = V + (long)b * K_ * F_ * S_ + (long)f0 * S_ + s0;

    // per-chunk fill (all 128 threads, 8 cp.async each)
    auto fill = [&](int c) {
        float* dst = Vb[c & 1];
        const float* src = Vg + (long)c * KC * F_ * S_;
        #pragma unroll
        for (int i = tid; i < KC * FI * (SI / 4); i += NT) {
            int k  = i / (FI * (SI / 4));
            int f  = (i / (SI / 4)) % FI;
            int s4 = i % (SI / 4);
            cp_async16(dst + (k * FI + f) * SI + s4 * 4,
                       src + ((long)k * F_ + f) * S_ + s4 * 4);
        }
        cp_commit();
    };

    // --- prefetch chunk 0 (latency hidden under softmax) ---
    fill(0);

    // --- softmax: 4 warps x 8 t's each, gather from L2-hot corr ---
    {
        int c0 = rIdx[lane];
        int c1 = rIdx[lane + 32];
        #pragma unroll
        for (int t = wid; t < T_; t += 4) {
            int row = tIdx[b * T_ + t];
            float v0 = __ldg(corr + row * N_ + c0);
            float v1 = __ldg(corr + row * N_ + c1);
            float m = fmaxf(v0, v1);
            #pragma unroll
            for (int off = 16; off > 0; off >>= 1)
                m = fmaxf(m, __shfl_xor_sync(0xffffffffu, m, off));
            float e0 = expf(v0 - m);
            float e1 = expf(v1 - m);
            float s = e0 + e1;
            #pragma unroll
            for (int off = 16; off > 0; off >>= 1)
                s += __shfl_xor_sync(0xffffffffu, s, off);
            float inv = 1.0f / s;
            attnF[lane * T_ + t]        = e0 * inv;
            attnF[(lane + 32) * T_ + t] = e1 * inv;
        }
    }

    // --- main loop: double-buffered k-chunks, ONE barrier per chunk ---
    const int sg = tid & 7;           // 0..7 : s-group (4 s each)
    const int fl = (tid >> 3) & 7;    // 0..7 : f within tile
    const int tq = tid >> 6;          // 0..1 : t-half
    const int t0 = tq * 16;

    ull acc[8][4];
    #pragma unroll
    for (int p = 0; p < 8; ++p)
        #pragma unroll
        for (int si = 0; si < 4; ++si) acc[p][si] = 0ULL;

    #pragma unroll
    for (int c = 0; c < NCHUNK; ++c) {
        cp_wait<0>();       // chunk c's fill complete (only group in flight)
        __syncthreads();    // publish chunk c (+attnF on c==0); certifies all
                            // warps finished chunk c-1 -> its buffer is free
        if (c + 1 < NCHUNK) fill(c + 1);   // overlaps compute of chunk c

        const float* Vc = Vb[c & 1];
        const float* aFc = attnF + c * KC * T_;
        #pragma unroll 4
        for (int k = 0; k < KC; ++k) {
            float4 vf = *(const float4*)(Vc + (k * FI + fl) * SI + sg * 4);
            ull vd0 = dup2(vf.x), vd1 = dup2(vf.y);
            ull vd2 = dup2(vf.z), vd3 = dup2(vf.w);
            const float* aF = aFc + k * T_ + t0;
            ulonglong2 a01 = *(const ulonglong2*)(aF);
            ulonglong2 a23 = *(const ulonglong2*)(aF + 4);
            ulonglong2 a45 = *(const ulonglong2*)(aF + 8);
            ulonglong2 a67 = *(const ulonglong2*)(aF + 12);
            fma2(acc[0][0], vd0, a01.x); fma2(acc[0][1], vd1, a01.x);
            fma2(acc[0][2], vd2, a01.x); fma2(acc[0][3], vd3, a01.x);
            fma2(acc[1][0], vd0, a01.y); fma2(acc[1][1], vd1, a01.y);
            fma2(acc[1][2], vd2, a01.y); fma2(acc[1][3], vd3, a01.y);
            fma2(acc[2][0], vd0, a23.x); fma2(acc[2][1], vd1, a23.x);
            fma2(acc[2][2], vd2, a23.x); fma2(acc[2][3], vd3, a23.x);
            fma2(acc[3][0], vd0, a23.y); fma2(acc[3][1], vd1, a23.y);
            fma2(acc[3][2], vd2, a23.y); fma2(acc[3][3], vd3, a23.y);
            fma2(acc[4][0], vd0, a45.x); fma2(acc[4][1], vd1, a45.x);
            fma2(acc[4][2], vd2, a45.x); fma2(acc[4][3], vd3, a45.x);
            fma2(acc[5][0], vd0, a45.y); fma2(acc[5][1], vd1, a45.y);
            fma2(acc[5][2], vd2, a45.y); fma2(acc[5][3], vd3, a45.y);
            fma2(acc[6][0], vd0, a67.x); fma2(acc[6][1], vd1, a67.x);
            fma2(acc[6][2], vd2, a67.x); fma2(acc[6][3], vd3, a67.x);
            fma2(acc[7][0], vd0, a67.y); fma2(acc[7][1], vd1, a67.y);
            fma2(acc[7][2], vd2, a67.y); fma2(acc[7][3], vd3, a67.y);
        }
    }
    __syncthreads();   // all warps done with last chunk (stg overlays Vbufs)

    // --- stage: stgU[tpair][s][10] (fl at 0..7, 2 pad)  [R6 verbatim] ---
    #pragma unroll
    for (int p = 0; p < 8; ++p) {
        int tp = tq * 8 + p;
        #pragma unroll
        for (int si = 0; si < 4; ++si) {
            int s = sg * 4 + si;
            stgU[(tp * SI + s) * 10 + fl] = acc[p][si];
        }
    }
    __syncthreads();

    // --- epilogue: per iter read 4 ull (2 x LDS.128) -> two float4 RMW ---
    #pragma unroll
    for (int i = tid; i < (T_ / 2) * SI * 2; i += NT) {
        int g  = i & 1;
        int s  = (i >> 1) & (SI - 1);
        int tp = i >> 6;
        const ull* src = &stgU[(tp * SI + s) * 10 + 4 * g];
        ulonglong2 u0 = *(const ulonglong2*)(src);       // f = 4g, 4g+1
        ulonglong2 u1 = *(const ulonglong2*)(src + 2);   // f = 4g+2, 4g+3
        float2 p0 = *(const float2*)&u0.x;  // (t_even, t_odd)
        float2 p1 = *(const float2*)&u0.y;
        float2 p2 = *(const float2*)&u1.x;
        float2 p3 = *(const float2*)&u1.y;

        long gi0 = (((long)b * T_ + 2 * tp)     * S_ + s0 + s) * F_ + f0 + 4 * g;
        long gi1 = (((long)b * T_ + 2 * tp + 1) * S_ + s0 + s) * F_ + f0 + 4 * g;
        float4 t4, c4;
        t4 = *(const float4*)(tgt + gi0);
        c4.x = p0.x + t4.x; c4.y = p1.x + t4.y;
        c4.z = p2.x + t4.z; c4.w = p3.x + t4.w;
        *(float4*)(out + gi0) = c4;
        t4 = *(const float4*)(tgt + gi1);
        c4.x = p0.y + t4.x; c4.y = p1.y + t4.y;
        c4.z = p2.y + t4.z; c4.w = p3.y + t4.w;
        *(float4*)(out + gi1) = c4;
    }
}

// ---------------------------------------------------------------------------
extern "C" void kernel_launch(void* const* d_in, const int* in_sizes, int n_in,
                              void* d_out, int out_size) {
    const float* tgt  = nullptr;   // 16777216
    const float* V    = nullptr;   // 33554432
    const float* corr = nullptr;   // 40000
    const int*   tIdx = nullptr;   // 256   (int32: jax x64 disabled)
    const int*   rIdx = nullptr;   // 64

    for (int i = 0; i < n_in; ++i) {
        switch (in_sizes[i]) {
            case 16777216: tgt  = (const float*)d_in[i]; break;
            case 33554432: V    = (const float*)d_in[i]; break;
            case 40000:    corr = (const float*)d_in[i]; break;
            case 256:      tIdx = (const int*)d_in[i]; break;
            case 64:       rIdx = (const int*)d_in[i]; break;
            default: break;
        }
    }

    cudaFuncSetAttribute(fusion_kernel,
                         cudaFuncAttributeMaxDynamicSharedMemorySize,
                         SMEM_TOTAL);

    dim3 grid(S_ / SI, F_ / FI, B_);
    fusion_kernel<<<grid, NT, SMEM_TOTAL>>>(tgt, V, corr, tIdx, rIdx,
                                            (float*)d_out);
}